// round 1
// baseline (speedup 1.0000x reference)
#include <cuda_runtime.h>
#include <cuda_bf16.h>

#define NN 50000
#define NE 800000
#define NG 256
#define F  64

// ---------------- scratch (device globals; no allocation allowed) ----------------
__device__ __align__(16) float g_h[NN * F];     // h = act(prev) @ W
__device__ __align__(16) float g_agg[NN * F];   // aggregation accumulator
__device__ __align__(16) float g_sums[NG * F];  // pooled sums
__device__ float g_cnt[NG];
__device__ float g_dinv[NN];                    // deg^-1/2
__device__ float g_invdeg[NN];                  // deg^-1
__device__ int   g_deg[NN];

// ---------------- helpers ----------------
__device__ __forceinline__ void red_add_v4(float* p, float4 v) {
    asm volatile("red.global.add.v4.f32 [%0], {%1, %2, %3, %4};"
                 :: "l"(p), "f"(v.x), "f"(v.y), "f"(v.z), "f"(v.w) : "memory");
}

__device__ __forceinline__ void fma4(float4& a, float v, const float4& w) {
    a.x = fmaf(v, w.x, a.x);
    a.y = fmaf(v, w.y, a.y);
    a.z = fmaf(v, w.z, a.z);
    a.w = fmaf(v, w.w, a.w);
}

// ---------------- kernels ----------------
__global__ void zero_kernel() {
    int i = blockIdx.x * blockDim.x + threadIdx.x;
    if (i < NN) g_deg[i] = 0;
    if (i < NG * F) g_sums[i] = 0.0f;
    if (i < NG) g_cnt[i] = 0.0f;
}

__global__ void deg_kernel(const int* __restrict__ dst) {
    int e = blockIdx.x * blockDim.x + threadIdx.x;
    if (e < NE) atomicAdd(&g_deg[dst[e]], 1);
}

__global__ void dinv_kernel() {
    int i = blockIdx.x * blockDim.x + threadIdx.x;
    if (i < NN) {
        float d = (float)(g_deg[i] + 1);   // +1 self loop
        g_dinv[i] = rsqrtf(d);
        g_invdeg[i] = 1.0f / d;
    }
}

// GEMM + self-loop init:
//   in = (FIRST ? x : relu(g_agg + b_prev))
//   h = in @ W ; agg = h * invdeg
// Block: 256 threads = 64 nodes x 4 parts (16 outputs per part).
template <bool FIRST>
__global__ void gemm_kernel(const float* __restrict__ x,
                            const float* __restrict__ W,
                            const float* __restrict__ bprev) {
    __shared__ float4 Ws[F * 16];   // 64 rows x 16 float4 (=64 cols)
    int tid = threadIdx.x;
    const float4* W4 = (const float4*)W;
#pragma unroll
    for (int i = tid; i < F * 16; i += 256) Ws[i] = W4[i];
    __syncthreads();

    int node = blockIdx.x * 64 + (tid >> 2);
    int part = tid & 3;
    if (node >= NN) return;

    const float4* xr = FIRST ? (const float4*)(x + (size_t)node * F)
                             : (const float4*)(g_agg + (size_t)node * F);
    const float4* b4 = (const float4*)bprev;

    float4 a0 = make_float4(0.f, 0.f, 0.f, 0.f);
    float4 a1 = a0, a2 = a0, a3 = a0;

#pragma unroll
    for (int k4 = 0; k4 < 16; ++k4) {
        float4 xv = xr[k4];
        if (!FIRST) {
            float4 bv = b4[k4];
            xv.x = fmaxf(xv.x + bv.x, 0.f);
            xv.y = fmaxf(xv.y + bv.y, 0.f);
            xv.z = fmaxf(xv.z + bv.z, 0.f);
            xv.w = fmaxf(xv.w + bv.w, 0.f);
        }
        float vs[4] = {xv.x, xv.y, xv.z, xv.w};
#pragma unroll
        for (int kk = 0; kk < 4; ++kk) {
            const float4* wrow = &Ws[(k4 * 4 + kk) * 16 + part * 4];
            float v = vs[kk];
            fma4(a0, v, wrow[0]);
            fma4(a1, v, wrow[1]);
            fma4(a2, v, wrow[2]);
            fma4(a3, v, wrow[3]);
        }
    }

    float id = g_invdeg[node];
    float4* hr = (float4*)(g_h + (size_t)node * F);
    float4* ar = (float4*)(g_agg + (size_t)node * F);
    int o = part * 4;
    hr[o + 0] = a0; hr[o + 1] = a1; hr[o + 2] = a2; hr[o + 3] = a3;
    float4 s0 = make_float4(a0.x * id, a0.y * id, a0.z * id, a0.w * id);
    float4 s1 = make_float4(a1.x * id, a1.y * id, a1.z * id, a1.w * id);
    float4 s2 = make_float4(a2.x * id, a2.y * id, a2.z * id, a2.w * id);
    float4 s3 = make_float4(a3.x * id, a3.y * id, a3.z * id, a3.w * id);
    ar[o + 0] = s0; ar[o + 1] = s1; ar[o + 2] = s2; ar[o + 3] = s3;
}

// Edge scatter: 16 lanes per edge, one float4 each.
__global__ void edge_kernel(const int* __restrict__ src, const int* __restrict__ dst) {
    int t = blockIdx.x * blockDim.x + threadIdx.x;
    int e = t >> 4;
    int l = t & 15;
    if (e >= NE) return;
    int s = src[e];
    int d = dst[e];
    float norm = g_dinv[s] * g_dinv[d];
    float4 m = ((const float4*)g_h)[(size_t)s * 16 + l];
    m.x *= norm; m.y *= norm; m.z *= norm; m.w *= norm;
    red_add_v4(g_agg + (size_t)d * F + l * 4, m);
}

// Pool: relu(agg + b3) accumulated into per-graph sums and counts.
__global__ void pool_kernel(const int* __restrict__ batch, const float* __restrict__ b3) {
    int t = blockIdx.x * blockDim.x + threadIdx.x;
    int node = t >> 4;
    int l = t & 15;
    if (node >= NN) return;
    int g = batch[node];
    float4 v = ((const float4*)g_agg)[(size_t)node * 16 + l];
    float4 bv = ((const float4*)b3)[l];
    v.x = fmaxf(v.x + bv.x, 0.f);
    v.y = fmaxf(v.y + bv.y, 0.f);
    v.z = fmaxf(v.z + bv.z, 0.f);
    v.w = fmaxf(v.w + bv.w, 0.f);
    red_add_v4(g_sums + (size_t)g * F + l * 4, v);
    if (l == 0) atomicAdd(&g_cnt[g], 1.0f);
}

// out[g] = (sums[g] . Wl) / max(cnt,1) + bl
__global__ void final_kernel(const float* __restrict__ Wl, const float* __restrict__ bl,
                             float* __restrict__ out) {
    int g = threadIdx.x;
    float c = fmaxf(g_cnt[g], 1.0f);
    float acc = 0.f;
#pragma unroll
    for (int f = 0; f < F; ++f) acc = fmaf(g_sums[g * F + f], Wl[f], acc);
    out[g] = acc / c + bl[0];
}

// ---------------- launch ----------------
extern "C" void kernel_launch(void* const* d_in, const int* in_sizes, int n_in,
                              void* d_out, int out_size) {
    const float* x   = (const float*)d_in[0];
    const int* src   = (const int*)d_in[1];
    const int* dst   = (const int*)d_in[2];
    const int* batch = (const int*)d_in[3];
    const float* W1 = (const float*)d_in[4];
    const float* b1 = (const float*)d_in[5];
    const float* W2 = (const float*)d_in[6];
    const float* b2 = (const float*)d_in[7];
    const float* W3 = (const float*)d_in[8];
    const float* b3 = (const float*)d_in[9];
    const float* Wl = (const float*)d_in[10];
    const float* bl = (const float*)d_in[11];
    float* out = (float*)d_out;

    const int NB_NODE = (NN + 255) / 256;        // 196
    const int NB_EDGE = (NE + 255) / 256;        // 3125
    const int NB_GEMM = (NN + 63) / 64;          // 782
    const int NB_ESC  = (NE * 16) / 256;         // 50000
    const int NB_POOL = (NN * 16 + 255) / 256;   // 3125

    zero_kernel<<<NB_NODE, 256>>>();
    deg_kernel<<<NB_EDGE, 256>>>(dst);
    dinv_kernel<<<NB_NODE, 256>>>();

    // layer 1
    gemm_kernel<true><<<NB_GEMM, 256>>>(x, W1, nullptr);
    edge_kernel<<<NB_ESC, 256>>>(src, dst);
    // layer 2 (fuses b1+relu on input)
    gemm_kernel<false><<<NB_GEMM, 256>>>(nullptr, W2, b1);
    edge_kernel<<<NB_ESC, 256>>>(src, dst);
    // layer 3 (fuses b2+relu on input)
    gemm_kernel<false><<<NB_GEMM, 256>>>(nullptr, W3, b2);
    edge_kernel<<<NB_ESC, 256>>>(src, dst);

    // pool (fuses b3+relu) + head
    pool_kernel<<<NB_POOL, 256>>>(batch, b3);
    final_kernel<<<1, 256>>>(Wl, bl, out);
}

// round 2
// speedup vs baseline: 1.3271x; 1.3271x over previous
#include <cuda_runtime.h>
#include <cuda_bf16.h>

#define NN 50000
#define NE 800000
#define NG 256
#define F  64

// ---------------- scratch (device globals; no allocation allowed) ----------------
__device__ __align__(16) float g_h[NN * F];     // h * dinv  (pre-scaled for edge gather)
__device__ __align__(16) float g_agg[NN * F];   // aggregation accumulator
__device__ __align__(16) float g_sums[NG * F];  // pooled sums
__device__ float g_cnt[NG];
__device__ float g_dinv[NN];                    // deg^-1/2
__device__ float g_invdeg[NN];                  // deg^-1
__device__ int   g_deg[NN];

// ---------------- helpers ----------------
__device__ __forceinline__ void red_add_v4(float* p, float4 v) {
    asm volatile("red.global.add.v4.f32 [%0], {%1, %2, %3, %4};"
                 :: "l"(p), "f"(v.x), "f"(v.y), "f"(v.z), "f"(v.w) : "memory");
}

// ---------------- kernels ----------------
__global__ void zero_kernel() {
    int i = blockIdx.x * blockDim.x + threadIdx.x;
    if (i < NN) g_deg[i] = 0;
    if (i < NG * F) g_sums[i] = 0.0f;
    if (i < NG) g_cnt[i] = 0.0f;
}

__global__ void deg_kernel(const int* __restrict__ dst) {
    int e = blockIdx.x * blockDim.x + threadIdx.x;
    if (e < NE) atomicAdd(&g_deg[dst[e]], 1);
}

__global__ void dinv_kernel() {
    int i = blockIdx.x * blockDim.x + threadIdx.x;
    if (i < NN) {
        float d = (float)(g_deg[i] + 1);   // +1 self loop
        g_dinv[i] = rsqrtf(d);
        g_invdeg[i] = 1.0f / d;
    }
}

// GEMM + self-loop init, register-blocked 4 rows/thread:
//   in = (FIRST ? x : relu(g_agg + b_prev))
//   a = in @ W ;  g_h = a * dinv ;  g_agg = a * invdeg
// Block: 256 threads = 64 quads x 4 parts; quad covers 4 consecutive nodes;
// part covers 16 output columns. Block covers 256 nodes.
template <bool FIRST>
__global__ __launch_bounds__(256) void gemm_kernel(const float* __restrict__ x,
                                                   const float* __restrict__ W,
                                                   const float* __restrict__ bprev) {
    __shared__ float4 Ws[F * 16];   // 64 rows x 16 float4 (=64 cols)
    int tid = threadIdx.x;
    const float4* W4 = (const float4*)W;
#pragma unroll
    for (int i = tid; i < F * 16; i += 256) Ws[i] = W4[i];
    __syncthreads();

    int part = tid & 3;
    int quad = tid >> 2;                      // 0..63
    int base = blockIdx.x * 256 + quad * 4;   // 4 consecutive nodes

    const float4* in4 = FIRST ? (const float4*)x : (const float4*)g_agg;
    const float4* b4 = (const float4*)bprev;

    float4 acc[4][4];
#pragma unroll
    for (int r = 0; r < 4; ++r)
#pragma unroll
        for (int j = 0; j < 4; ++j) acc[r][j] = make_float4(0.f, 0.f, 0.f, 0.f);

#pragma unroll
    for (int k4 = 0; k4 < 16; ++k4) {
        float4 bv;
        if (!FIRST) bv = b4[k4];
        float xs[4][4];
#pragma unroll
        for (int r = 0; r < 4; ++r) {
            int node = base + r;
            float4 xv = make_float4(0.f, 0.f, 0.f, 0.f);
            if (node < NN) {
                xv = in4[(size_t)node * 16 + k4];
                if (!FIRST) {
                    xv.x = fmaxf(xv.x + bv.x, 0.f);
                    xv.y = fmaxf(xv.y + bv.y, 0.f);
                    xv.z = fmaxf(xv.z + bv.z, 0.f);
                    xv.w = fmaxf(xv.w + bv.w, 0.f);
                }
            }
            xs[r][0] = xv.x; xs[r][1] = xv.y; xs[r][2] = xv.z; xs[r][3] = xv.w;
        }
#pragma unroll
        for (int kk = 0; kk < 4; ++kk) {
            const float4* wrow = &Ws[(k4 * 4 + kk) * 16 + part * 4];
            float4 w0 = wrow[0], w1 = wrow[1], w2 = wrow[2], w3 = wrow[3];
#pragma unroll
            for (int r = 0; r < 4; ++r) {
                float v = xs[r][kk];
                acc[r][0].x = fmaf(v, w0.x, acc[r][0].x);
                acc[r][0].y = fmaf(v, w0.y, acc[r][0].y);
                acc[r][0].z = fmaf(v, w0.z, acc[r][0].z);
                acc[r][0].w = fmaf(v, w0.w, acc[r][0].w);
                acc[r][1].x = fmaf(v, w1.x, acc[r][1].x);
                acc[r][1].y = fmaf(v, w1.y, acc[r][1].y);
                acc[r][1].z = fmaf(v, w1.z, acc[r][1].z);
                acc[r][1].w = fmaf(v, w1.w, acc[r][1].w);
                acc[r][2].x = fmaf(v, w2.x, acc[r][2].x);
                acc[r][2].y = fmaf(v, w2.y, acc[r][2].y);
                acc[r][2].z = fmaf(v, w2.z, acc[r][2].z);
                acc[r][2].w = fmaf(v, w2.w, acc[r][2].w);
                acc[r][3].x = fmaf(v, w3.x, acc[r][3].x);
                acc[r][3].y = fmaf(v, w3.y, acc[r][3].y);
                acc[r][3].z = fmaf(v, w3.z, acc[r][3].z);
                acc[r][3].w = fmaf(v, w3.w, acc[r][3].w);
            }
        }
    }

#pragma unroll
    for (int r = 0; r < 4; ++r) {
        int node = base + r;
        if (node >= NN) continue;
        float dv = g_dinv[node];
        float id = g_invdeg[node];
        float4* hr = (float4*)(g_h + (size_t)node * F) + part * 4;
        float4* ar = (float4*)(g_agg + (size_t)node * F) + part * 4;
#pragma unroll
        for (int j = 0; j < 4; ++j) {
            float4 a = acc[r][j];
            hr[j] = make_float4(a.x * dv, a.y * dv, a.z * dv, a.w * dv);
            ar[j] = make_float4(a.x * id, a.y * id, a.z * id, a.w * id);
        }
    }
}

// Edge scatter: 16 lanes per edge, one float4 each.
// g_h already holds h*dinv[src], so msg = g_h[src] * dinv[dst].
__global__ void edge_kernel(const int* __restrict__ src, const int* __restrict__ dst) {
    int t = blockIdx.x * blockDim.x + threadIdx.x;
    int e = t >> 4;
    int l = t & 15;
    if (e >= NE) return;
    int s = __ldg(src + e);
    int d = __ldg(dst + e);
    float norm = g_dinv[d];
    float4 m = ((const float4*)g_h)[(size_t)s * 16 + l];
    m.x *= norm; m.y *= norm; m.z *= norm; m.w *= norm;
    red_add_v4(g_agg + (size_t)d * F + l * 4, m);
}

// Pool: relu(agg + b3) accumulated into per-graph sums and counts.
__global__ void pool_kernel(const int* __restrict__ batch, const float* __restrict__ b3) {
    int t = blockIdx.x * blockDim.x + threadIdx.x;
    int node = t >> 4;
    int l = t & 15;
    if (node >= NN) return;
    int g = batch[node];
    float4 v = ((const float4*)g_agg)[(size_t)node * 16 + l];
    float4 bv = ((const float4*)b3)[l];
    v.x = fmaxf(v.x + bv.x, 0.f);
    v.y = fmaxf(v.y + bv.y, 0.f);
    v.z = fmaxf(v.z + bv.z, 0.f);
    v.w = fmaxf(v.w + bv.w, 0.f);
    red_add_v4(g_sums + (size_t)g * F + l * 4, v);
    if (l == 0) atomicAdd(&g_cnt[g], 1.0f);
}

// out[g] = (sums[g] . Wl) / max(cnt,1) + bl
__global__ void final_kernel(const float* __restrict__ Wl, const float* __restrict__ bl,
                             float* __restrict__ out) {
    int g = threadIdx.x;
    float c = fmaxf(g_cnt[g], 1.0f);
    float acc = 0.f;
#pragma unroll
    for (int f = 0; f < F; ++f) acc = fmaf(g_sums[g * F + f], Wl[f], acc);
    out[g] = acc / c + bl[0];
}

// ---------------- launch ----------------
extern "C" void kernel_launch(void* const* d_in, const int* in_sizes, int n_in,
                              void* d_out, int out_size) {
    const float* x   = (const float*)d_in[0];
    const int* src   = (const int*)d_in[1];
    const int* dst   = (const int*)d_in[2];
    const int* batch = (const int*)d_in[3];
    const float* W1 = (const float*)d_in[4];
    const float* b1 = (const float*)d_in[5];
    const float* W2 = (const float*)d_in[6];
    const float* b2 = (const float*)d_in[7];
    const float* W3 = (const float*)d_in[8];
    const float* b3 = (const float*)d_in[9];
    const float* Wl = (const float*)d_in[10];
    const float* bl = (const float*)d_in[11];
    float* out = (float*)d_out;

    const int NB_NODE = (NN + 255) / 256;        // 196
    const int NB_EDGE = (NE + 255) / 256;        // 3125
    const int NB_GEMM = (NN + 255) / 256;        // 196 (256 nodes per block)
    const int NB_ESC  = (NE * 16) / 256;         // 50000
    const int NB_POOL = (NN * 16 + 255) / 256;   // 3125

    zero_kernel<<<NB_NODE, 256>>>();
    deg_kernel<<<NB_EDGE, 256>>>(dst);
    dinv_kernel<<<NB_NODE, 256>>>();

    // layer 1
    gemm_kernel<true><<<NB_GEMM, 256>>>(x, W1, nullptr);
    edge_kernel<<<NB_ESC, 256>>>(src, dst);
    // layer 2 (fuses b1+relu on input)
    gemm_kernel<false><<<NB_GEMM, 256>>>(nullptr, W2, b1);
    edge_kernel<<<NB_ESC, 256>>>(src, dst);
    // layer 3 (fuses b2+relu on input)
    gemm_kernel<false><<<NB_GEMM, 256>>>(nullptr, W3, b2);
    edge_kernel<<<NB_ESC, 256>>>(src, dst);

    // pool (fuses b3+relu) + head
    pool_kernel<<<NB_POOL, 256>>>(batch, b3);
    final_kernel<<<1, 256>>>(Wl, bl, out);
}

// round 3
// speedup vs baseline: 1.9535x; 1.4721x over previous
#include <cuda_runtime.h>
#include <cuda_bf16.h>

#define NN 50000
#define NE 800000
#define NG 256
#define F  64
#define NB_SCAN 196   // ceil(NN/256)

// ---------------- scratch ----------------
__device__ __align__(16) float g_h[NN * F];     // h * dinv[src] (pre-scaled)
__device__ __align__(16) float g_agg[NN * F];   // self-loop init, then full agg
__device__ __align__(16) float g_sums[NG * F];
__device__ float g_cnt[NG];
__device__ float g_dinv[NN];
__device__ float g_invdeg[NN];
__device__ int   g_deg[NN];
__device__ int   g_rowstart[NN];
__device__ int   g_cursor[NN];
__device__ int   g_bsum[NB_SCAN];
__device__ int   g_boff[NB_SCAN];
__device__ int   g_ssorted[NE];

__device__ __forceinline__ void red_add_v4(float* p, float4 v) {
    asm volatile("red.global.add.v4.f32 [%0], {%1, %2, %3, %4};"
                 :: "l"(p), "f"(v.x), "f"(v.y), "f"(v.z), "f"(v.w) : "memory");
}

// ---------------- prep kernels ----------------
__global__ void zero_kernel() {
    int i = blockIdx.x * blockDim.x + threadIdx.x;
    if (i < NN) g_deg[i] = 0;
    if (i < NG * F) g_sums[i] = 0.0f;
    if (i < NG) g_cnt[i] = 0.0f;
}

__global__ void deg_kernel(const int* __restrict__ dst) {
    int e = blockIdx.x * blockDim.x + threadIdx.x;
    if (e < NE) atomicAdd(&g_deg[dst[e]], 1);
}

__global__ void dinv_kernel(const int* __restrict__ batch) {
    int i = blockIdx.x * blockDim.x + threadIdx.x;
    if (i < NN) {
        float d = (float)(g_deg[i] + 1);
        g_dinv[i] = rsqrtf(d);
        g_invdeg[i] = 1.0f / d;
        atomicAdd(&g_cnt[batch[i]], 1.0f);
    }
}

// exclusive scan of g_deg, 3-phase
__global__ void scan1_kernel() {
    __shared__ int s[2][256];
    int tid = threadIdx.x;
    int i = blockIdx.x * 256 + tid;
    int v = (i < NN) ? g_deg[i] : 0;
    s[0][tid] = v;
    __syncthreads();
    int cur = 0;
#pragma unroll
    for (int off = 1; off < 256; off <<= 1) {
        int val = s[cur][tid];
        if (tid >= off) val += s[cur][tid - off];
        s[cur ^ 1][tid] = val;
        cur ^= 1;
        __syncthreads();
    }
    // inclusive -> exclusive
    int excl = (tid == 0) ? 0 : s[cur][tid - 1];
    if (i < NN) g_rowstart[i] = excl;
    if (tid == 255) g_bsum[blockIdx.x] = s[cur][255];
}

__global__ void scan2_kernel() {
    __shared__ int s[2][256];
    int tid = threadIdx.x;
    s[0][tid] = (tid < NB_SCAN) ? g_bsum[tid] : 0;
    __syncthreads();
    int cur = 0;
#pragma unroll
    for (int off = 1; off < 256; off <<= 1) {
        int val = s[cur][tid];
        if (tid >= off) val += s[cur][tid - off];
        s[cur ^ 1][tid] = val;
        cur ^= 1;
        __syncthreads();
    }
    if (tid < NB_SCAN) g_boff[tid] = (tid == 0) ? 0 : s[cur][tid - 1];
}

__global__ void scan3_kernel() {
    int i = blockIdx.x * 256 + threadIdx.x;
    if (i < NN) {
        int rs = g_rowstart[i] + g_boff[blockIdx.x];
        g_rowstart[i] = rs;
        g_cursor[i] = rs;
    }
}

__global__ void scatter_kernel(const int* __restrict__ src, const int* __restrict__ dst) {
    int e = blockIdx.x * blockDim.x + threadIdx.x;
    if (e < NE) {
        int d = dst[e];
        int pos = atomicAdd(&g_cursor[d], 1);
        g_ssorted[pos] = src[e];
    }
}

// ---------------- GEMM + self-loop init ----------------
// in = (FIRST ? x : relu(g_agg + b_prev)); a = in @ W
// g_h = a * dinv; g_agg = a * invdeg
// Block: 128 threads = 32 quads x 4 parts; covers 128 nodes.
template <bool FIRST>
__global__ __launch_bounds__(128) void gemm_kernel(const float* __restrict__ x,
                                                   const float* __restrict__ W,
                                                   const float* __restrict__ bprev) {
    __shared__ float4 Ws[F * 16];
    int tid = threadIdx.x;
    const float4* W4 = (const float4*)W;
#pragma unroll
    for (int i = tid; i < F * 16; i += 128) Ws[i] = W4[i];
    __syncthreads();

    int part = tid & 3;
    int quad = tid >> 2;                      // 0..31
    int base = blockIdx.x * 128 + quad * 4;

    const float4* in4 = FIRST ? (const float4*)x : (const float4*)g_agg;
    const float4* b4 = (const float4*)bprev;

    float4 acc[4][4];
#pragma unroll
    for (int r = 0; r < 4; ++r)
#pragma unroll
        for (int j = 0; j < 4; ++j) acc[r][j] = make_float4(0.f, 0.f, 0.f, 0.f);

#pragma unroll
    for (int k4 = 0; k4 < 16; ++k4) {
        float4 bv;
        if (!FIRST) bv = b4[k4];
        float xs[4][4];
#pragma unroll
        for (int r = 0; r < 4; ++r) {
            int node = base + r;
            float4 xv = make_float4(0.f, 0.f, 0.f, 0.f);
            if (node < NN) {
                xv = in4[(size_t)node * 16 + k4];
                if (!FIRST) {
                    xv.x = fmaxf(xv.x + bv.x, 0.f);
                    xv.y = fmaxf(xv.y + bv.y, 0.f);
                    xv.z = fmaxf(xv.z + bv.z, 0.f);
                    xv.w = fmaxf(xv.w + bv.w, 0.f);
                }
            }
            xs[r][0] = xv.x; xs[r][1] = xv.y; xs[r][2] = xv.z; xs[r][3] = xv.w;
        }
#pragma unroll
        for (int kk = 0; kk < 4; ++kk) {
            const float4* wrow = &Ws[(k4 * 4 + kk) * 16 + part * 4];
            float4 w0 = wrow[0], w1 = wrow[1], w2 = wrow[2], w3 = wrow[3];
#pragma unroll
            for (int r = 0; r < 4; ++r) {
                float v = xs[r][kk];
                acc[r][0].x = fmaf(v, w0.x, acc[r][0].x);
                acc[r][0].y = fmaf(v, w0.y, acc[r][0].y);
                acc[r][0].z = fmaf(v, w0.z, acc[r][0].z);
                acc[r][0].w = fmaf(v, w0.w, acc[r][0].w);
                acc[r][1].x = fmaf(v, w1.x, acc[r][1].x);
                acc[r][1].y = fmaf(v, w1.y, acc[r][1].y);
                acc[r][1].z = fmaf(v, w1.z, acc[r][1].z);
                acc[r][1].w = fmaf(v, w1.w, acc[r][1].w);
                acc[r][2].x = fmaf(v, w2.x, acc[r][2].x);
                acc[r][2].y = fmaf(v, w2.y, acc[r][2].y);
                acc[r][2].z = fmaf(v, w2.z, acc[r][2].z);
                acc[r][2].w = fmaf(v, w2.w, acc[r][2].w);
                acc[r][3].x = fmaf(v, w3.x, acc[r][3].x);
                acc[r][3].y = fmaf(v, w3.y, acc[r][3].y);
                acc[r][3].z = fmaf(v, w3.z, acc[r][3].z);
                acc[r][3].w = fmaf(v, w3.w, acc[r][3].w);
            }
        }
    }

#pragma unroll
    for (int r = 0; r < 4; ++r) {
        int node = base + r;
        if (node >= NN) continue;
        float dv = g_dinv[node];
        float id = g_invdeg[node];
        float4* hr = (float4*)(g_h + (size_t)node * F) + part * 4;
        float4* ar = (float4*)(g_agg + (size_t)node * F) + part * 4;
#pragma unroll
        for (int j = 0; j < 4; ++j) {
            float4 a = acc[r][j];
            hr[j] = make_float4(a.x * dv, a.y * dv, a.z * dv, a.w * dv);
            ar[j] = make_float4(a.x * id, a.y * id, a.z * id, a.w * id);
        }
    }
}

// ---------------- CSR aggregation: one 16-lane group per dst ----------------
// g_agg[d] = self_term + dinv[d] * sum_{s in row(d)} g_h[s]
// LAST: additionally pool relu(out + b3) into g_sums per graph.
template <bool LAST>
__global__ __launch_bounds__(256) void agg_kernel(const int* __restrict__ batch,
                                                  const float* __restrict__ b3) {
    int t = blockIdx.x * blockDim.x + threadIdx.x;
    int d = t >> 4;
    int l = t & 15;
    if (d >= NN) return;
    int start = g_rowstart[d];
    int n = g_deg[d];
    const float4* h4 = (const float4*)g_h;

    float4 acc = make_float4(0.f, 0.f, 0.f, 0.f);
    int i = 0;
    for (; i + 2 <= n; i += 2) {
        int s0 = g_ssorted[start + i];
        int s1 = g_ssorted[start + i + 1];
        float4 v0 = h4[(size_t)s0 * 16 + l];
        float4 v1 = h4[(size_t)s1 * 16 + l];
        acc.x += v0.x + v1.x;
        acc.y += v0.y + v1.y;
        acc.z += v0.z + v1.z;
        acc.w += v0.w + v1.w;
    }
    if (i < n) {
        int s0 = g_ssorted[start + i];
        float4 v0 = h4[(size_t)s0 * 16 + l];
        acc.x += v0.x; acc.y += v0.y; acc.z += v0.z; acc.w += v0.w;
    }

    float dd = g_dinv[d];
    float4* ar = (float4*)g_agg + (size_t)d * 16 + l;
    float4 self = *ar;
    float4 out = make_float4(fmaf(acc.x, dd, self.x),
                             fmaf(acc.y, dd, self.y),
                             fmaf(acc.z, dd, self.z),
                             fmaf(acc.w, dd, self.w));
    if (!LAST) {
        *ar = out;
    } else {
        float4 bv = ((const float4*)b3)[l];
        out.x = fmaxf(out.x + bv.x, 0.f);
        out.y = fmaxf(out.y + bv.y, 0.f);
        out.z = fmaxf(out.z + bv.z, 0.f);
        out.w = fmaxf(out.w + bv.w, 0.f);
        int g = batch[d];
        red_add_v4(g_sums + (size_t)g * F + l * 4, out);
    }
}

// out[g] = (sums[g] . Wl) / max(cnt,1) + bl
__global__ void final_kernel(const float* __restrict__ Wl, const float* __restrict__ bl,
                             float* __restrict__ out) {
    int g = threadIdx.x;
    float c = fmaxf(g_cnt[g], 1.0f);
    float acc = 0.f;
#pragma unroll
    for (int f = 0; f < F; ++f) acc = fmaf(g_sums[g * F + f], Wl[f], acc);
    out[g] = acc / c + bl[0];
}

// ---------------- launch ----------------
extern "C" void kernel_launch(void* const* d_in, const int* in_sizes, int n_in,
                              void* d_out, int out_size) {
    const float* x   = (const float*)d_in[0];
    const int* src   = (const int*)d_in[1];
    const int* dst   = (const int*)d_in[2];
    const int* batch = (const int*)d_in[3];
    const float* W1 = (const float*)d_in[4];
    const float* b1 = (const float*)d_in[5];
    const float* W2 = (const float*)d_in[6];
    const float* b2 = (const float*)d_in[7];
    const float* W3 = (const float*)d_in[8];
    const float* b3 = (const float*)d_in[9];
    const float* Wl = (const float*)d_in[10];
    const float* bl = (const float*)d_in[11];
    float* out = (float*)d_out;

    const int NB_NODE = (NN + 255) / 256;        // 196
    const int NB_EDGE = (NE + 255) / 256;        // 3125
    const int NB_GEMM = (NN + 127) / 128;        // 391
    const int NB_AGG  = (NN * 16 + 255) / 256;   // 3125

    // prep: degrees, dinv, CSR build
    zero_kernel<<<NB_NODE, 256>>>();
    deg_kernel<<<NB_EDGE, 256>>>(dst);
    dinv_kernel<<<NB_NODE, 256>>>(batch);
    scan1_kernel<<<NB_SCAN, 256>>>();
    scan2_kernel<<<1, 256>>>();
    scan3_kernel<<<NB_SCAN, 256>>>();
    scatter_kernel<<<NB_EDGE, 256>>>(src, dst);

    // layer 1
    gemm_kernel<true><<<NB_GEMM, 128>>>(x, W1, nullptr);
    agg_kernel<false><<<NB_AGG, 256>>>(batch, b3);
    // layer 2
    gemm_kernel<false><<<NB_GEMM, 128>>>(nullptr, W2, b1);
    agg_kernel<false><<<NB_AGG, 256>>>(batch, b3);
    // layer 3 (+ fused pool)
    gemm_kernel<false><<<NB_GEMM, 128>>>(nullptr, W3, b2);
    agg_kernel<true><<<NB_AGG, 256>>>(batch, b3);

    final_kernel<<<1, 256>>>(Wl, bl, out);
}